// round 12
// baseline (speedup 1.0000x reference)
#include <cuda_runtime.h>

#define THREADS 512          // 16 warps
#define N_TOK 98
#define CDIM 128
#define HEADS 4
#define LWIN 512

#define CVT_TF32(u, f) asm("cvt.rna.tf32.f32 %0, %1;" : "=r"(u) : "f"(f))

__device__ __forceinline__ void mma_tf32(float* d, const unsigned* a, const unsigned* b) {
    asm volatile("mma.sync.aligned.m16n8k8.row.col.f32.tf32.tf32.f32 "
        "{%0,%1,%2,%3}, {%4,%5,%6,%7}, {%8,%9}, {%0,%1,%2,%3};"
        : "+f"(d[0]), "+f"(d[1]), "+f"(d[2]), "+f"(d[3])
        : "r"(a[0]), "r"(a[1]), "r"(a[2]), "r"(a[3]), "r"(b[0]), "r"(b[1]));
}

// smem layout (floats; all mma operands stored as tf32 bit patterns, PAIR-PACKED):
//  xs  [0     .. 12544) : x 98x128: row i, pair pos(c)=((c>>3)*4|(c&3)), e=(c>>2)&1,
//                         addr = i*128 + ((pos+2i)&63)*2 + e     (later O, same packing)
//  q_s [12544 .. 25088) : 4 x [98 x 16 pairs x 2]: addr = h*3136 + i*32 + ((pos+2i)&15)*2 + e
//  kT  [25088 .. 38400) : 4 x [16 pairs(d) x 104 x 2]: addr = h*3328 + pos*208 + j*2 + e
//  vT  [38400 .. 51712) : 4 x [32 x 52 pairs(j) x 2]: addr = h*3328 + n*104 + jpos*2 + e
//  wt  [51712 .. 57984) : 16 x 392 (qkv W chunk) / 16 x 136 (proj W chunk), scalar
#define XS_OFF 0
#define Q_OFF  12544
#define KT_OFF 25088
#define VT_OFF 38400
#define WT_OFF 51712
#define SMEM_FLOATS 57984

// precomputed rel-pos bias table: bias[h][i][j]
__device__ float g_bias[HEADS * N_TOK * N_TOK];

__global__ void bias_precompute_kernel(const float* __restrict__ pe)
{
    int idx = blockIdx.x * blockDim.x + threadIdx.x;
    if (idx >= HEADS * N_TOK * N_TOK) return;
    int h = idx / (N_TOK * N_TOK);
    int r = idx % (N_TOK * N_TOK);
    int i = r / N_TOK, j = r % N_TOK;
    int ti = i / 49, rem = i % 49, hi = rem / 7, wi = rem % 7;
    int tj = j / 49, remj = j % 49, hj = remj / 7, wj = remj % 7;
    int ridx = (ti - tj + 1) * 169 + (hi - hj + 6) * 13 + (wi - wj + 6);
    g_bias[idx] = pe[h * 507 + ridx];
}

__global__ __launch_bounds__(THREADS, 1)
void win_attn_kernel(const float* __restrict__ x,
                     const float* __restrict__ mask,
                     const float* __restrict__ qkv_w,
                     const float* __restrict__ qkv_b,
                     const float* __restrict__ proj_w,
                     const float* __restrict__ proj_b,
                     float* __restrict__ out)
{
    extern __shared__ float sm[];
    float* xs  = sm + XS_OFF;
    float* q_s = sm + Q_OFF;
    float* kT  = sm + KT_OFF;
    float* vT  = sm + VT_OFF;
    float* wt  = sm + WT_OFF;

    const int b   = blockIdx.x;
    const int tid = threadIdx.x;
    const int tx  = tid & 31;
    const int ty  = tid >> 5;            // warp id 0..15
    const int gid = tx >> 2;             // 0..7 (mma group)
    const int tig = tx & 3;              // 0..3 (thread-in-group)
    const float scale = 0.17677669529663687f;  // 32^-0.5

    // ---------------- load x tile (tf32 bits, pair-packed) + zero kT/vT ----------------
    {
        // zero the whole kT+vT region (pads must be 0; valid parts overwritten later)
        float4 z4 = make_float4(0.f, 0.f, 0.f, 0.f);
        for (int idx = tid; idx < (2 * 13312) / 4; idx += THREADS)
            ((float4*)kT)[idx] = z4;

        const float4* xg4 = (const float4*)(x + (size_t)b * (N_TOK * CDIM));
        for (int idx = tid; idx < N_TOK * 32; idx += THREADS) {
            int i = idx >> 5, j4 = idx & 31;
            float4 v = xg4[i * 32 + j4];
            float vv[4] = {v.x, v.y, v.z, v.w};
            #pragma unroll
            for (int t = 0; t < 4; ++t) {
                unsigned u; CVT_TF32(u, vv[t]);
                int c = j4 * 4 + t;
                int pos = ((c >> 3) << 2) | (c & 3);
                int e = (c >> 2) & 1;
                xs[i * 128 + ((pos + 2 * i) & 63) * 2 + e] = __uint_as_float(u);
            }
        }
    }

    // ---------------- QKV GEMM via tf32 mma: C[98x384] = X @ W^T ----------------
    {
        float facc[7][3][4];
        #pragma unroll
        for (int mt = 0; mt < 7; ++mt)
            #pragma unroll
            for (int nt = 0; nt < 3; ++nt)
                #pragma unroll
                for (int e = 0; e < 4; ++e) facc[mt][nt][e] = 0.f;

        float wreg[12];
        #pragma unroll
        for (int u = 0; u < 12; ++u) {
            int idx = tid + u * THREADS;
            int kk = idx & 15, cc = idx >> 4;
            wreg[u] = qkv_w[cc * 128 + kk];           // chunk 0
        }

        const int cb = ty * 24;
        for (int ch = 0; ch < 8; ++ch) {
            __syncthreads();                           // wt free / x+zero STS done
            #pragma unroll
            for (int u = 0; u < 12; ++u) {
                int idx = tid + u * THREADS;
                int kk = idx & 15, cc = idx >> 4;
                unsigned uu; CVT_TF32(uu, wreg[u]);
                wt[kk * 392 + cc] = __uint_as_float(uu);
            }
            if (ch < 7) {
                #pragma unroll
                for (int u = 0; u < 12; ++u) {
                    int idx = tid + u * THREADS;
                    int kk = idx & 15, cc = idx >> 4;
                    wreg[u] = qkv_w[cc * 128 + (ch + 1) * 16 + kk];
                }
            }
            __syncthreads();

            #pragma unroll
            for (int ks = 0; ks < 2; ++ks) {
                int koff = ks * 8;
                unsigned bfr[3][2];
                #pragma unroll
                for (int nt = 0; nt < 3; ++nt) {
                    bfr[nt][0] = __float_as_uint(wt[(koff + tig) * 392 + cb + nt * 8 + gid]);
                    bfr[nt][1] = __float_as_uint(wt[(koff + tig + 4) * 392 + cb + nt * 8 + gid]);
                }
                int ppos = (2 * ch + ks) * 4 + tig;
                #pragma unroll
                for (int mt = 0; mt < 7; ++mt) {
                    int i0 = mt * 16 + gid, i1 = i0 + 8;
                    uint2 a02 = *(const uint2*)(xs + i0 * 128 + ((ppos + 2 * i0) & 63) * 2);
                    uint2 a13 = *(const uint2*)(xs + i1 * 128 + ((ppos + 2 * i1) & 63) * 2);
                    unsigned afr[4] = {a02.x, a13.x, a02.y, a13.y};
                    #pragma unroll
                    for (int nt = 0; nt < 3; ++nt)
                        mma_tf32(facc[mt][nt], afr, bfr[nt]);
                }
            }
        }

        // epilogue: bias add, tf32 bits, scatter to paired q/kT/vT
        #pragma unroll
        for (int nt = 0; nt < 3; ++nt) {
            int c0 = cb + nt * 8 + 2 * tig;    // even; (c0,c0+1) same 32-block
            int sect = c0 >> 7;
            int hh   = (c0 >> 5) & 3;
            int d0   = c0 & 31;
            float bi0 = qkv_b[c0], bi1 = qkv_b[c0 + 1];
            #pragma unroll
            for (int mt = 0; mt < 7; ++mt) {
                #pragma unroll
                for (int half = 0; half < 2; ++half) {
                    int i = mt * 16 + gid + half * 8;
                    if (i >= 98) continue;
                    float v0 = facc[mt][nt][half * 2 + 0] + bi0;
                    float v1 = facc[mt][nt][half * 2 + 1] + bi1;
                    #pragma unroll
                    for (int q = 0; q < 2; ++q) {
                        int d = d0 + q;
                        float vv = q ? v1 : v0;
                        unsigned u;
                        if (sect == 0) {
                            CVT_TF32(u, vv * scale);
                            int pos = ((d >> 3) << 2) | (d & 3);
                            int e = (d >> 2) & 1;
                            q_s[hh * 3136 + i * 32 + ((pos + 2 * i) & 15) * 2 + e]
                                = __uint_as_float(u);
                        } else if (sect == 1) {
                            CVT_TF32(u, vv);
                            int pos = ((d >> 3) << 2) | (d & 3);
                            int e = (d >> 2) & 1;
                            kT[hh * 3328 + pos * 208 + i * 2 + e] = __uint_as_float(u);
                        } else {
                            CVT_TF32(u, vv);
                            int jpos = ((i >> 3) << 2) | (i & 3);
                            int e = (i >> 2) & 1;
                            vT[hh * 3328 + d * 104 + jpos * 2 + e] = __uint_as_float(u);
                        }
                    }
                }
            }
        }
    }
    __syncthreads();   // q/kT/vT visible; xs free for reuse as O

    // ---------------- attention: 28 warp-tasks (head, m-tile), NO barriers ----------------
    const float* maskp = mask + (size_t)(b & (LWIN - 1)) * (N_TOK * N_TOK);
    const int qsrc0 = (tx & ~3) | (tig >> 1);
    const int qsrc1 = qsrc0 | 2;
    const bool odd = tig & 1;

    for (int task = ty; task < 28; task += 16) {
        int h = task & 3, mt = task >> 2;
        int i0 = mt * 16 + gid, i1 = i0 + 8;
        bool val0 = i0 < 98, val1 = i1 < 98;
        const float* qh = q_s + h * 3136;
        const float* kh = kT + h * 3328;
        const float* vh = vT + h * 3328;
        const float* bh = g_bias + h * (N_TOK * N_TOK);

        // ---- init S frags with bias + mask (LDGs issue BEFORE mma) ----
        float s[13][4];
        #pragma unroll
        for (int nt = 0; nt < 13; ++nt) {
            int j0 = nt * 8 + 2 * tig;
            if (j0 < 98) {
                if (val0) {
                    float2 bb = *(const float2*)(bh + i0 * 98 + j0);
                    float2 mm = *(const float2*)(maskp + i0 * 98 + j0);
                    s[nt][0] = bb.x + mm.x;
                    s[nt][1] = bb.y + mm.y;
                } else { s[nt][0] = s[nt][1] = 0.f; }
                if (val1) {
                    float2 bb = *(const float2*)(bh + i1 * 98 + j0);
                    float2 mm = *(const float2*)(maskp + i1 * 98 + j0);
                    s[nt][2] = bb.x + mm.x;
                    s[nt][3] = bb.y + mm.y;
                } else { s[nt][2] = s[nt][3] = 0.f; }
            } else {
                // kT pad is zeroed, so mma adds 0 here and -1e30 survives
                s[nt][0] = s[nt][1] = s[nt][2] = s[nt][3] = -1e30f;
            }
        }

        // ---- S += q k^T (paired 64-bit fragment loads) ----
        #pragma unroll
        for (int ksi = 0; ksi < 4; ++ksi) {
            int pos = ksi * 4 + tig;
            uint2 a02 = *(const uint2*)(qh + i0 * 32 + ((pos + 2 * i0) & 15) * 2);
            uint2 a13 = *(const uint2*)(qh + i1 * 32 + ((pos + 2 * i1) & 15) * 2);
            unsigned a[4] = {a02.x, a13.x, a02.y, a13.y};
            #pragma unroll
            for (int nt = 0; nt < 13; ++nt) {
                uint2 b2 = *(const uint2*)(kh + pos * 208 + (nt * 8 + gid) * 2);
                unsigned bb[2] = {b2.x, b2.y};
                mma_tf32(s[nt], a, bb);
            }
        }

        // ---- softmax on fragments ----
        float m0 = -1e30f, m1 = -1e30f;
        #pragma unroll
        for (int nt = 0; nt < 13; ++nt) {
            m0 = fmaxf(m0, fmaxf(s[nt][0], s[nt][1]));
            m1 = fmaxf(m1, fmaxf(s[nt][2], s[nt][3]));
        }
        m0 = fmaxf(m0, __shfl_xor_sync(0xffffffffu, m0, 1));
        m0 = fmaxf(m0, __shfl_xor_sync(0xffffffffu, m0, 2));
        m1 = fmaxf(m1, __shfl_xor_sync(0xffffffffu, m1, 1));
        m1 = fmaxf(m1, __shfl_xor_sync(0xffffffffu, m1, 2));

        float z0 = 0.f, z1 = 0.f;
        #pragma unroll
        for (int nt = 0; nt < 13; ++nt) {
            s[nt][0] = __expf(s[nt][0] - m0);
            s[nt][1] = __expf(s[nt][1] - m0);
            s[nt][2] = __expf(s[nt][2] - m1);
            s[nt][3] = __expf(s[nt][3] - m1);
            z0 += s[nt][0] + s[nt][1];
            z1 += s[nt][2] + s[nt][3];
        }
        z0 += __shfl_xor_sync(0xffffffffu, z0, 1);
        z0 += __shfl_xor_sync(0xffffffffu, z0, 2);
        z1 += __shfl_xor_sync(0xffffffffu, z1, 1);
        z1 += __shfl_xor_sync(0xffffffffu, z1, 2);
        float inv0 = 1.f / z0, inv1 = 1.f / z1;

        // ---- O = P @ V ; P C-frags -> A-frags via quad shuffles ----
        float o[4][4];
        #pragma unroll
        for (int nt = 0; nt < 4; ++nt)
            #pragma unroll
            for (int e = 0; e < 4; ++e) o[nt][e] = 0.f;

        #pragma unroll
        for (int jt = 0; jt < 13; ++jt) {
            float t00 = __shfl_sync(0xffffffffu, s[jt][0], qsrc0);
            float t01 = __shfl_sync(0xffffffffu, s[jt][1], qsrc0);
            float t10 = __shfl_sync(0xffffffffu, s[jt][2], qsrc0);
            float t11 = __shfl_sync(0xffffffffu, s[jt][3], qsrc0);
            float t20 = __shfl_sync(0xffffffffu, s[jt][0], qsrc1);
            float t21 = __shfl_sync(0xffffffffu, s[jt][1], qsrc1);
            float t30 = __shfl_sync(0xffffffffu, s[jt][2], qsrc1);
            float t31 = __shfl_sync(0xffffffffu, s[jt][3], qsrc1);
            unsigned pa[4];
            CVT_TF32(pa[0], odd ? t01 : t00);
            CVT_TF32(pa[1], odd ? t11 : t10);
            CVT_TF32(pa[2], odd ? t21 : t20);
            CVT_TF32(pa[3], odd ? t31 : t30);
            int jpos = jt * 4 + tig;
            #pragma unroll
            for (int nt = 0; nt < 4; ++nt) {
                uint2 v2 = *(const uint2*)(vh + (nt * 8 + gid) * 104 + jpos * 2);
                unsigned bb[2] = {v2.x, v2.y};
                mma_tf32(o[nt], pa, bb);
            }
        }

        // ---- store O (normalized, tf32 bits) into pair-packed xs ----
        #pragma unroll
        for (int nt = 0; nt < 4; ++nt) {
            int C0 = h * 32 + nt * 8 + 2 * tig;
            #pragma unroll
            for (int half = 0; half < 2; ++half) {
                int i = half ? i1 : i0;
                if (half ? !val1 : !val0) continue;
                float inv = half ? inv1 : inv0;
                #pragma unroll
                for (int q = 0; q < 2; ++q) {
                    int C = C0 + q;
                    unsigned u;
                    CVT_TF32(u, o[nt][half * 2 + q] * inv);
                    int pos = ((C >> 3) << 2) | (C & 3);
                    int e = (C >> 2) & 1;
                    xs[i * 128 + ((pos + 2 * i) & 63) * 2 + e] = __uint_as_float(u);
                }
            }
        }
    }

    // ---------------- projection via tf32 mma: out = O @ Wp^T + b ----------------
    {
        float facc[7][4];
        #pragma unroll
        for (int mt = 0; mt < 7; ++mt)
            #pragma unroll
            for (int e = 0; e < 4; ++e) facc[mt][e] = 0.f;

        float preg[4];
        #pragma unroll
        for (int u = 0; u < 4; ++u) {
            int idx = tid + u * THREADS;
            int kk = idx & 15, cc = idx >> 4;
            preg[u] = proj_w[cc * 128 + kk];          // chunk 0
        }

        const int cb = ty * 8;
        for (int ch = 0; ch < 8; ++ch) {
            __syncthreads();   // first iter: covers O writes; later: wt reuse
            #pragma unroll
            for (int u = 0; u < 4; ++u) {
                int idx = tid + u * THREADS;
                int kk = idx & 15, cc = idx >> 4;
                unsigned uu; CVT_TF32(uu, preg[u]);
                wt[kk * 136 + cc] = __uint_as_float(uu);
            }
            if (ch < 7) {
                #pragma unroll
                for (int u = 0; u < 4; ++u) {
                    int idx = tid + u * THREADS;
                    int kk = idx & 15, cc = idx >> 4;
                    preg[u] = proj_w[cc * 128 + (ch + 1) * 16 + kk];
                }
            }
            __syncthreads();

            #pragma unroll
            for (int ksi = 0; ksi < 2; ++ksi) {
                int koff = ksi * 8;
                unsigned bfr[2];
                bfr[0] = __float_as_uint(wt[(koff + tig) * 136 + cb + gid]);
                bfr[1] = __float_as_uint(wt[(koff + tig + 4) * 136 + cb + gid]);
                int ppos = (2 * ch + ksi) * 4 + tig;
                #pragma unroll
                for (int mt = 0; mt < 7; ++mt) {
                    int i0 = mt * 16 + gid, i1 = i0 + 8;
                    uint2 a02 = *(const uint2*)(xs + i0 * 128 + ((ppos + 2 * i0) & 63) * 2);
                    uint2 a13 = *(const uint2*)(xs + i1 * 128 + ((ppos + 2 * i1) & 63) * 2);
                    unsigned afr[4] = {a02.x, a13.x, a02.y, a13.y};
                    mma_tf32(facc[mt], afr, bfr);
                }
            }
        }

        float pb0 = proj_b[cb + 2 * tig];
        float pb1 = proj_b[cb + 2 * tig + 1];
        float* outb = out + (size_t)b * (N_TOK * CDIM);
        #pragma unroll
        for (int mt = 0; mt < 7; ++mt) {
            #pragma unroll
            for (int half = 0; half < 2; ++half) {
                int i = mt * 16 + gid + half * 8;
                if (i >= 98) continue;
                float2 v;
                v.x = facc[mt][half * 2 + 0] + pb0;
                v.y = facc[mt][half * 2 + 1] + pb1;
                *(float2*)(outb + i * 128 + cb + 2 * tig) = v;
            }
        }
    }
}

extern "C" void kernel_launch(void* const* d_in, const int* in_sizes, int n_in,
                              void* d_out, int out_size)
{
    const float* x      = (const float*)d_in[0];
    const float* mask   = (const float*)d_in[1];
    const float* qkv_w  = (const float*)d_in[2];
    const float* qkv_b  = (const float*)d_in[3];
    const float* pe     = (const float*)d_in[4];
    const float* proj_w = (const float*)d_in[5];
    const float* proj_b = (const float*)d_in[6];
    float* out = (float*)d_out;

    bias_precompute_kernel<<<(HEADS * N_TOK * N_TOK + 255) / 256, 256>>>(pe);

    const int smem_bytes = SMEM_FLOATS * sizeof(float);   // 231936
    cudaFuncSetAttribute(win_attn_kernel,
                         cudaFuncAttributeMaxDynamicSharedMemorySize, smem_bytes);

    int nwin = in_sizes[0] / (N_TOK * CDIM);              // 2048
    win_attn_kernel<<<nwin, THREADS, smem_bytes>>>(
        x, mask, qkv_w, qkv_b, proj_w, proj_b, out);
}

// round 13
// speedup vs baseline: 1.1859x; 1.1859x over previous
#include <cuda_runtime.h>

#define THREADS 512          // 16 warps
#define N_TOK 98
#define CDIM 128
#define HEADS 4
#define LWIN 512

#define CVT_TF32(u, f) asm("cvt.rna.tf32.f32 %0, %1;" : "=r"(u) : "f"(f))

__device__ __forceinline__ void mma_tf32(float* d, const unsigned* a, const unsigned* b) {
    asm volatile("mma.sync.aligned.m16n8k8.row.col.f32.tf32.tf32.f32 "
        "{%0,%1,%2,%3}, {%4,%5,%6,%7}, {%8,%9}, {%0,%1,%2,%3};"
        : "+f"(d[0]), "+f"(d[1]), "+f"(d[2]), "+f"(d[3])
        : "r"(a[0]), "r"(a[1]), "r"(a[2]), "r"(a[3]), "r"(b[0]), "r"(b[1]));
}

// smem layout (floats; tf32 operands stored as raw bit patterns):
//  xs  [0     .. 12544) : x tile 98x128 tf32 bits, swizzle col' = (c+4i)&127; later O bits
//  q_s [12544 .. 25088) : 4 x 98 x 32, tf32 bits, swizzle d' = (d+4i)&31
//  kT  [25088 .. 38400) : 4 x 32 x 104 (k transposed [d][j], tf32 bits; j pad zeroed)
//  vT  [38400 .. 51712) : 4 x 32 x 104 (v transposed [d][j], tf32 bits; j pad zeroed)
//  wt  [51712 .. 57984) : 16 x 392 qkv W chunk (buf0); buf1 overlaps vT start (dead
//                         during QKV mainloop). Proj: buf0 at WT_OFF, buf1 at Q_OFF.
#define XS_OFF 0
#define Q_OFF  12544
#define KT_OFF 25088
#define VT_OFF 38400
#define WT_OFF 51712
#define SMEM_FLOATS 57984

// precomputed rel-pos bias table: bias[h][i][j]
__device__ float g_bias[HEADS * N_TOK * N_TOK];

__global__ void bias_precompute_kernel(const float* __restrict__ pe)
{
    int idx = blockIdx.x * blockDim.x + threadIdx.x;
    if (idx >= HEADS * N_TOK * N_TOK) return;
    int h = idx / (N_TOK * N_TOK);
    int r = idx % (N_TOK * N_TOK);
    int i = r / N_TOK, j = r % N_TOK;
    int ti = i / 49, rem = i % 49, hi = rem / 7, wi = rem % 7;
    int tj = j / 49, remj = j % 49, hj = remj / 7, wj = remj % 7;
    int ridx = (ti - tj + 1) * 169 + (hi - hj + 6) * 13 + (wi - wj + 6);
    g_bias[idx] = pe[h * 507 + ridx];
}

__global__ __launch_bounds__(THREADS, 1)
void win_attn_kernel(const float* __restrict__ x,
                     const float* __restrict__ mask,
                     const float* __restrict__ qkv_w,
                     const float* __restrict__ qkv_b,
                     const float* __restrict__ proj_w,
                     const float* __restrict__ proj_b,
                     float* __restrict__ out)
{
    extern __shared__ float sm[];
    float* xs  = sm + XS_OFF;
    float* q_s = sm + Q_OFF;
    float* kT  = sm + KT_OFF;
    float* vT  = sm + VT_OFF;

    const int b   = blockIdx.x;
    const int tid = threadIdx.x;
    const int tx  = tid & 31;
    const int ty  = tid >> 5;            // warp id 0..15
    const int gid = tx >> 2;             // 0..7 (mma group)
    const int tig = tx & 3;              // 0..3 (thread-in-group)
    const float scale = 0.17677669529663687f;  // 32^-0.5

    // ---------------- load x tile (tf32 bits once) + zero kT pads ----------------
    {
        const float4* xg4 = (const float4*)(x + (size_t)b * (N_TOK * CDIM));
        for (int idx = tid; idx < N_TOK * 32; idx += THREADS) {
            int i = idx >> 5, j4 = idx & 31;
            float4 v = xg4[i * 32 + j4];
            uint4 u;
            CVT_TF32(u.x, v.x); CVT_TF32(u.y, v.y);
            CVT_TF32(u.z, v.z); CVT_TF32(u.w, v.w);
            int sw = ((j4 * 4 + 4 * i) & 127) >> 2;
            ((uint4*)xs)[i * 32 + sw] = u;
        }
        // kT pads only; vT pads zeroed after the QKV mainloop (buf1 overlaps vT)
        for (int idx = tid; idx < HEADS * 32 * 6; idx += THREADS) {
            int h = idx / 192, rem = idx % 192, d = rem / 6, e = rem % 6;
            kT[h * 3328 + d * 104 + 98 + e] = 0.f;
        }
    }

    // ---------------- QKV GEMM via tf32 mma, double-buffered weight chunks ----------------
    {
        float facc[7][3][4];
        #pragma unroll
        for (int mt = 0; mt < 7; ++mt)
            #pragma unroll
            for (int nt = 0; nt < 3; ++nt)
                #pragma unroll
                for (int e = 0; e < 4; ++e) facc[mt][nt][e] = 0.f;

        float* wb0 = sm + WT_OFF;
        float* wb1 = sm + VT_OFF;          // dead until epilogue

        float wreg[12];
        #pragma unroll
        for (int u = 0; u < 12; ++u) {     // LDG chunk 0
            int idx = tid + u * THREADS;
            int kk = idx & 15, cc = idx >> 4;
            wreg[u] = qkv_w[cc * 128 + kk];
        }
        #pragma unroll
        for (int u = 0; u < 12; ++u) {     // STS chunk 0 -> buf0
            int idx = tid + u * THREADS;
            int kk = idx & 15, cc = idx >> 4;
            unsigned uu; CVT_TF32(uu, wreg[u]);
            wb0[kk * 392 + cc] = __uint_as_float(uu);
        }
        __syncthreads();                   // xs + kT pads + buf0 ready

        const int cb = ty * 24;
        for (int ch = 0; ch < 8; ++ch) {
            float* cur = (ch & 1) ? wb1 : wb0;
            if (ch < 7) {                  // LDG next chunk early (latency hidden by mma)
                #pragma unroll
                for (int u = 0; u < 12; ++u) {
                    int idx = tid + u * THREADS;
                    int kk = idx & 15, cc = idx >> 4;
                    wreg[u] = qkv_w[cc * 128 + (ch + 1) * 16 + kk];
                }
            }

            #pragma unroll
            for (int ks = 0; ks < 2; ++ks) {
                int koff = ks * 8;
                unsigned bfr[3][2];
                #pragma unroll
                for (int nt = 0; nt < 3; ++nt) {
                    bfr[nt][0] = __float_as_uint(cur[(koff + tig) * 392 + cb + nt * 8 + gid]);
                    bfr[nt][1] = __float_as_uint(cur[(koff + tig + 4) * 392 + cb + nt * 8 + gid]);
                }
                #pragma unroll
                for (int mt = 0; mt < 7; ++mt) {
                    int i0 = mt * 16 + gid, i1 = i0 + 8;
                    int c = ch * 16 + koff + tig;
                    unsigned afr[4];
                    afr[0] = __float_as_uint(xs[i0 * 128 + ((c + 4 * i0) & 127)]);
                    afr[1] = __float_as_uint(xs[i1 * 128 + ((c + 4 * i1) & 127)]);
                    afr[2] = __float_as_uint(xs[i0 * 128 + ((c + 4 + 4 * i0) & 127)]);
                    afr[3] = __float_as_uint(xs[i1 * 128 + ((c + 4 + 4 * i1) & 127)]);
                    #pragma unroll
                    for (int nt = 0; nt < 3; ++nt)
                        mma_tf32(facc[mt][nt], afr, bfr[nt]);
                }
            }

            if (ch < 7) {                  // STS next chunk into the other buffer
                float* nxt = (ch & 1) ? wb0 : wb1;
                #pragma unroll
                for (int u = 0; u < 12; ++u) {
                    int idx = tid + u * THREADS;
                    int kk = idx & 15, cc = idx >> 4;
                    unsigned uu; CVT_TF32(uu, wreg[u]);
                    nxt[kk * 392 + cc] = __uint_as_float(uu);
                }
            }
            __syncthreads();               // one barrier per chunk
        }

        // vT pads (buf1 region dead now)
        for (int idx = tid; idx < HEADS * 32 * 6; idx += THREADS) {
            int h = idx / 192, rem = idx % 192, d = rem / 6, e = rem % 6;
            vT[h * 3328 + d * 104 + 98 + e] = 0.f;
        }

        // epilogue: bias add, convert to tf32 bits, scatter to q/kT/vT
        #pragma unroll
        for (int nt = 0; nt < 3; ++nt) {
            int c0 = cb + nt * 8 + 2 * tig;    // even; (c0,c0+1) same 32-block
            int sect = c0 >> 7;
            int hh   = (c0 >> 5) & 3;
            int d0   = c0 & 31;
            float bi0 = qkv_b[c0], bi1 = qkv_b[c0 + 1];
            #pragma unroll
            for (int mt = 0; mt < 7; ++mt) {
                #pragma unroll
                for (int half = 0; half < 2; ++half) {
                    int i = mt * 16 + gid + half * 8;
                    if (i >= 98) continue;
                    float v0 = facc[mt][nt][half * 2 + 0] + bi0;
                    float v1 = facc[mt][nt][half * 2 + 1] + bi1;
                    unsigned u0, u1;
                    if (sect == 0) {
                        CVT_TF32(u0, v0 * scale);
                        CVT_TF32(u1, v1 * scale);
                        q_s[hh * 3136 + i * 32 + ((d0 + 4 * i) & 31)]     = __uint_as_float(u0);
                        q_s[hh * 3136 + i * 32 + ((d0 + 1 + 4 * i) & 31)] = __uint_as_float(u1);
                    } else if (sect == 1) {
                        CVT_TF32(u0, v0);
                        CVT_TF32(u1, v1);
                        kT[hh * 3328 + d0 * 104 + i]       = __uint_as_float(u0);
                        kT[hh * 3328 + (d0 + 1) * 104 + i] = __uint_as_float(u1);
                    } else {
                        CVT_TF32(u0, v0);
                        CVT_TF32(u1, v1);
                        vT[hh * 3328 + d0 * 104 + i]       = __uint_as_float(u0);
                        vT[hh * 3328 + (d0 + 1) * 104 + i] = __uint_as_float(u1);
                    }
                }
            }
        }
    }
    __syncthreads();   // q/kT/vT visible; xs free for reuse as O

    // ---------------- attention: 28 warp-tasks (head, m-tile), NO barriers ----------------
    const float* maskp = mask + (size_t)(b & (LWIN - 1)) * (N_TOK * N_TOK);
    const int qsrc0 = (tx & ~3) | (tig >> 1);
    const int qsrc1 = qsrc0 | 2;
    const bool odd = tig & 1;

    for (int task = ty; task < 28; task += 16) {
        int h = task & 3, mt = task >> 2;
        int i0 = mt * 16 + gid, i1 = i0 + 8;
        bool val0 = i0 < 98, val1 = i1 < 98;
        const float* qh = q_s + h * 3136;
        const float* kh = kT + h * 3328;
        const float* vh = vT + h * 3328;
        const float* bh = g_bias + h * (N_TOK * N_TOK);

        // ---- init S frags with bias + mask (LDGs issue BEFORE mma, latency hidden) ----
        float s[13][4];
        #pragma unroll
        for (int nt = 0; nt < 13; ++nt) {
            int j0 = nt * 8 + 2 * tig;
            if (j0 < 98) {   // j0 even -> j0+1 <= 97
                if (val0) {
                    float2 bb = *(const float2*)(bh + i0 * 98 + j0);
                    float2 mm = *(const float2*)(maskp + i0 * 98 + j0);
                    s[nt][0] = bb.x + mm.x;
                    s[nt][1] = bb.y + mm.y;
                } else { s[nt][0] = s[nt][1] = 0.f; }
                if (val1) {
                    float2 bb = *(const float2*)(bh + i1 * 98 + j0);
                    float2 mm = *(const float2*)(maskp + i1 * 98 + j0);
                    s[nt][2] = bb.x + mm.x;
                    s[nt][3] = bb.y + mm.y;
                } else { s[nt][2] = s[nt][3] = 0.f; }
            } else {
                // kT pad is zeroed, so mma adds 0 here and -1e30 survives
                s[nt][0] = s[nt][1] = s[nt][2] = s[nt][3] = -1e30f;
            }
        }

        // ---- S += q k^T (tf32 mma) ----
        #pragma unroll
        for (int ks = 0; ks < 4; ++ks) {
            int d = ks * 8 + tig;
            unsigned a[4];
            a[0] = __float_as_uint(qh[i0 * 32 + ((d + 4 * i0) & 31)]);
            a[1] = __float_as_uint(qh[i1 * 32 + ((d + 4 * i1) & 31)]);
            a[2] = __float_as_uint(qh[i0 * 32 + ((d + 4 + 4 * i0) & 31)]);
            a[3] = __float_as_uint(qh[i1 * 32 + ((d + 4 + 4 * i1) & 31)]);
            #pragma unroll
            for (int nt = 0; nt < 13; ++nt) {
                unsigned bb[2];
                bb[0] = __float_as_uint(kh[d * 104 + nt * 8 + gid]);
                bb[1] = __float_as_uint(kh[(d + 4) * 104 + nt * 8 + gid]);
                mma_tf32(s[nt], a, bb);
            }
        }

        // ---- softmax on fragments ----
        float m0 = -1e30f, m1 = -1e30f;
        #pragma unroll
        for (int nt = 0; nt < 13; ++nt) {
            m0 = fmaxf(m0, fmaxf(s[nt][0], s[nt][1]));
            m1 = fmaxf(m1, fmaxf(s[nt][2], s[nt][3]));
        }
        m0 = fmaxf(m0, __shfl_xor_sync(0xffffffffu, m0, 1));
        m0 = fmaxf(m0, __shfl_xor_sync(0xffffffffu, m0, 2));
        m1 = fmaxf(m1, __shfl_xor_sync(0xffffffffu, m1, 1));
        m1 = fmaxf(m1, __shfl_xor_sync(0xffffffffu, m1, 2));

        float z0 = 0.f, z1 = 0.f;
        #pragma unroll
        for (int nt = 0; nt < 13; ++nt) {
            s[nt][0] = __expf(s[nt][0] - m0);
            s[nt][1] = __expf(s[nt][1] - m0);
            s[nt][2] = __expf(s[nt][2] - m1);
            s[nt][3] = __expf(s[nt][3] - m1);
            z0 += s[nt][0] + s[nt][1];
            z1 += s[nt][2] + s[nt][3];
        }
        z0 += __shfl_xor_sync(0xffffffffu, z0, 1);
        z0 += __shfl_xor_sync(0xffffffffu, z0, 2);
        z1 += __shfl_xor_sync(0xffffffffu, z1, 1);
        z1 += __shfl_xor_sync(0xffffffffu, z1, 2);
        float inv0 = 1.f / z0, inv1 = 1.f / z1;

        // ---- O = P @ V (tf32 mma); P C-frags -> A-frags via quad shuffles ----
        float o[4][4];
        #pragma unroll
        for (int nt = 0; nt < 4; ++nt)
            #pragma unroll
            for (int e = 0; e < 4; ++e) o[nt][e] = 0.f;

        #pragma unroll
        for (int jt = 0; jt < 13; ++jt) {
            float t00 = __shfl_sync(0xffffffffu, s[jt][0], qsrc0);
            float t01 = __shfl_sync(0xffffffffu, s[jt][1], qsrc0);
            float t10 = __shfl_sync(0xffffffffu, s[jt][2], qsrc0);
            float t11 = __shfl_sync(0xffffffffu, s[jt][3], qsrc0);
            float t20 = __shfl_sync(0xffffffffu, s[jt][0], qsrc1);
            float t21 = __shfl_sync(0xffffffffu, s[jt][1], qsrc1);
            float t30 = __shfl_sync(0xffffffffu, s[jt][2], qsrc1);
            float t31 = __shfl_sync(0xffffffffu, s[jt][3], qsrc1);
            unsigned pa[4];
            CVT_TF32(pa[0], odd ? t01 : t00);   // P[gid][8jt+tig]
            CVT_TF32(pa[1], odd ? t11 : t10);   // P[gid+8][8jt+tig]
            CVT_TF32(pa[2], odd ? t21 : t20);   // P[gid][8jt+tig+4]
            CVT_TF32(pa[3], odd ? t31 : t30);   // P[gid+8][8jt+tig+4]
            #pragma unroll
            for (int nt = 0; nt < 4; ++nt) {
                unsigned bb[2];
                bb[0] = __float_as_uint(vh[(nt * 8 + gid) * 104 + jt * 8 + tig]);
                bb[1] = __float_as_uint(vh[(nt * 8 + gid) * 104 + jt * 8 + tig + 4]);
                mma_tf32(o[nt], pa, bb);
            }
        }

        // ---- store O (normalized, tf32 bits) into xs, swizzle col' = (C+4i)&127 ----
        #pragma unroll
        for (int nt = 0; nt < 4; ++nt) {
            int C = h * 32 + nt * 8 + 2 * tig;
            if (val0) {
                unsigned u0, u1;
                CVT_TF32(u0, o[nt][0] * inv0);
                CVT_TF32(u1, o[nt][1] * inv0);
                float2 w2; w2.x = __uint_as_float(u0); w2.y = __uint_as_float(u1);
                *(float2*)(xs + i0 * 128 + ((C + 4 * i0) & 127)) = w2;
            }
            if (val1) {
                unsigned u0, u1;
                CVT_TF32(u0, o[nt][2] * inv1);
                CVT_TF32(u1, o[nt][3] * inv1);
                float2 w2; w2.x = __uint_as_float(u0); w2.y = __uint_as_float(u1);
                *(float2*)(xs + i1 * 128 + ((C + 4 * i1) & 127)) = w2;
            }
        }
    }

    // ---------------- projection via tf32 mma, double-buffered weight chunks ----------------
    {
        float facc[7][4];
        #pragma unroll
        for (int mt = 0; mt < 7; ++mt)
            #pragma unroll
            for (int e = 0; e < 4; ++e) facc[mt][e] = 0.f;

        float* pb0 = sm + WT_OFF;
        float* pb1 = sm + Q_OFF;           // q_s dead after attention

        float preg[4];
        #pragma unroll
        for (int u = 0; u < 4; ++u) {      // LDG chunk 0
            int idx = tid + u * THREADS;
            int kk = idx & 15, cc = idx >> 4;
            preg[u] = proj_w[cc * 128 + kk];
        }
        #pragma unroll
        for (int u = 0; u < 4; ++u) {      // STS chunk 0 -> buf0 (wt region, unused in attn)
            int idx = tid + u * THREADS;
            int kk = idx & 15, cc = idx >> 4;
            unsigned uu; CVT_TF32(uu, preg[u]);
            pb0[kk * 136 + cc] = __uint_as_float(uu);
        }
        __syncthreads();                   // covers all O writes + buf0

        const int cb = ty * 8;
        for (int ch = 0; ch < 8; ++ch) {
            float* cur = (ch & 1) ? pb1 : pb0;
            if (ch < 7) {
                #pragma unroll
                for (int u = 0; u < 4; ++u) {
                    int idx = tid + u * THREADS;
                    int kk = idx & 15, cc = idx >> 4;
                    preg[u] = proj_w[cc * 128 + (ch + 1) * 16 + kk];
                }
            }

            #pragma unroll
            for (int ksi = 0; ksi < 2; ++ksi) {
                int koff = ksi * 8;
                unsigned bfr[2];
                bfr[0] = __float_as_uint(cur[(koff + tig) * 136 + cb + gid]);
                bfr[1] = __float_as_uint(cur[(koff + tig + 4) * 136 + cb + gid]);
                #pragma unroll
                for (int mt = 0; mt < 7; ++mt) {
                    int i0 = mt * 16 + gid, i1 = i0 + 8;
                    int c = ch * 16 + koff + tig;
                    unsigned afr[4];
                    afr[0] = __float_as_uint(xs[i0 * 128 + ((c + 4 * i0) & 127)]);
                    afr[1] = __float_as_uint(xs[i1 * 128 + ((c + 4 * i1) & 127)]);
                    afr[2] = __float_as_uint(xs[i0 * 128 + ((c + 4 + 4 * i0) & 127)]);
                    afr[3] = __float_as_uint(xs[i1 * 128 + ((c + 4 + 4 * i1) & 127)]);
                    mma_tf32(facc[mt], afr, bfr);
                }
            }

            if (ch < 7) {
                float* nxt = (ch & 1) ? pb0 : pb1;
                #pragma unroll
                for (int u = 0; u < 4; ++u) {
                    int idx = tid + u * THREADS;
                    int kk = idx & 15, cc = idx >> 4;
                    unsigned uu; CVT_TF32(uu, preg[u]);
                    nxt[kk * 136 + cc] = __uint_as_float(uu);
                }
                __syncthreads();
            }
        }

        float pb0v = proj_b[cb + 2 * tig];
        float pb1v = proj_b[cb + 2 * tig + 1];
        float* outb = out + (size_t)b * (N_TOK * CDIM);
        #pragma unroll
        for (int mt = 0; mt < 7; ++mt) {
            #pragma unroll
            for (int half = 0; half < 2; ++half) {
                int i = mt * 16 + gid + half * 8;
                if (i >= 98) continue;
                float2 v;
                v.x = facc[mt][half * 2 + 0] + pb0v;
                v.y = facc[mt][half * 2 + 1] + pb1v;
                *(float2*)(outb + i * 128 + cb + 2 * tig) = v;
            }
        }
    }
}

extern "C" void kernel_launch(void* const* d_in, const int* in_sizes, int n_in,
                              void* d_out, int out_size)
{
    const float* x      = (const float*)d_in[0];
    const float* mask   = (const float*)d_in[1];
    const float* qkv_w  = (const float*)d_in[2];
    const float* qkv_b  = (const float*)d_in[3];
    const float* pe     = (const float*)d_in[4];
    const float* proj_w = (const float*)d_in[5];
    const float* proj_b = (const float*)d_in[6];
    float* out = (float*)d_out;

    bias_precompute_kernel<<<(HEADS * N_TOK * N_TOK + 255) / 256, 256>>>(pe);

    const int smem_bytes = SMEM_FLOATS * sizeof(float);   // 231936
    cudaFuncSetAttribute(win_attn_kernel,
                         cudaFuncAttributeMaxDynamicSharedMemorySize, smem_bytes);

    int nwin = in_sizes[0] / (N_TOK * CDIM);              // 2048
    win_attn_kernel<<<nwin, THREADS, smem_bytes>>>(
        x, mask, qkv_w, qkv_b, proj_w, proj_b, out);
}